// round 1
// baseline (speedup 1.0000x reference)
#include <cuda_runtime.h>

// InstanceConv on GB300 (sm_103a), fp32 baseline with packed f32x2 FMA.
// out[b,o,y,x] = (9/cnt) * sum_{tap,c} s[tap]*W[o,c,tap]*inp[b,c,y+dy,x+dx] + bias[o]
// mask_out[b,0,y,x] = mask[b,y,x]
//
// B=8, C=64, OC=64, H=W=128, K=3, pad=1, stride=1.

#define BATCH 8
#define CH 64
#define OC 64
#define HDIM 128
#define WDIM 128
#define TILE_W 64

#define WS_FLOATS (9 * 64 * 64)          // 36864: [tap][c][o]
#define IN_FLOATS (3 * 64 * (TILE_W+2))  // 12672: [row][c][padded x]
#define MK_FLOATS (3 * (TILE_W+2))       // 198:   [row][padded x]
#define SMEM_FLOATS (WS_FLOATS + IN_FLOATS + MK_FLOATS)
#define SMEM_BYTES (SMEM_FLOATS * 4)

#define OUT_MASK_OFF (BATCH * OC * HDIM * WDIM)   // 8388608

typedef unsigned long long ull;

__device__ float g_wt[WS_FLOATS];

__device__ __forceinline__ ull pack2(float a, float b) {
    ull r;
    asm("mov.b64 %0, {%1, %2};" : "=l"(r) : "f"(a), "f"(b));
    return r;
}

__device__ __forceinline__ ull fma2(ull a, ull b, ull c) {
    ull d;
    asm("fma.rn.f32x2 %0, %1, %2, %3;" : "=l"(d) : "l"(a), "l"(b), "l"(c));
    return d;
}

__device__ __forceinline__ float2 unpack2(ull v) {
    float2 r;
    asm("mov.b64 {%0, %1}, %2;" : "=f"(r.x), "=f"(r.y) : "l"(v));
    return r;
}

// One-time weight transpose: conv[o][c][ky][kx] -> g_wt[tap][c][o].
// Makes the main kernel's weight staging fully coalesced and its smem
// reads (64 consecutive floats per (tap,c)) conflict-free.
__global__ void wt_transpose(const float* __restrict__ conv) {
    int i = blockIdx.x * 256 + threadIdx.x;
    if (i < WS_FLOATS) {
        int o   = i & 63;
        int c   = (i >> 6) & 63;
        int tap = i >> 12;
        g_wt[i] = conv[(o * 64 + c) * 9 + tap];
    }
}

__global__ __launch_bounds__(256, 1)
void instconv_kernel(const float* __restrict__ inp,
                     const float* __restrict__ mask,
                     const float* __restrict__ bias,
                     float* __restrict__ out) {
    extern __shared__ float sm[];
    float* sWs = sm;                          // [9][64][64]
    float* sIn = sm + WS_FLOATS;              // [3][64][66]
    float* sM  = sm + WS_FLOATS + IN_FLOATS;  // [3][66]

    const int tid = threadIdx.x;
    const int b  = blockIdx.z;
    const int y  = blockIdx.y;
    const int x0 = blockIdx.x * TILE_W;

    // ---- stage weights (coalesced float4 copies from pre-transposed g_wt) ----
    {
        const float4* gw4 = reinterpret_cast<const float4*>(g_wt);
        float4* sw4 = reinterpret_cast<float4*>(sWs);
        #pragma unroll 4
        for (int i = tid; i < WS_FLOATS / 4; i += 256) sw4[i] = gw4[i];
    }

    // ---- stage input window: 3 rows x 64 ch x (TILE_W+2) padded pixels ----
    for (int i = tid; i < IN_FLOATS; i += 256) {
        int xx = i % (TILE_W + 2);
        int rc = i / (TILE_W + 2);
        int c  = rc & 63;
        int r  = rc >> 6;
        int ys = y + r - 1;
        int xs = x0 + xx - 1;
        float v = 0.0f;  // OOB value is multiplied by s=0 later; 0 is safe
        if ((unsigned)ys < (unsigned)HDIM && (unsigned)xs < (unsigned)WDIM)
            v = inp[((b * CH + c) * HDIM + ys) * WDIM + xs];
        sIn[i] = v;
    }

    // ---- stage mask window (fill -1 OOB: never equals center, so s=0) ----
    for (int i = tid; i < MK_FLOATS; i += 256) {
        int xx = i % (TILE_W + 2);
        int r  = i / (TILE_W + 2);
        int ys = y + r - 1;
        int xs = x0 + xx - 1;
        float v = -1.0f;
        if ((unsigned)ys < (unsigned)HDIM && (unsigned)xs < (unsigned)WDIM)
            v = mask[(b * HDIM + ys) * WDIM + xs];
        sM[i] = v;
    }
    __syncthreads();

    // thread tile: 4 output channels x 4 pixels
    const int po = tid & 15;   // o-group
    const int pp = tid >> 4;   // pixel-group
    const int o0 = po * 4;
    const int t0 = pp * 4;

    float m0[4];
    #pragma unroll
    for (int p = 0; p < 4; ++p) m0[p] = sM[(TILE_W + 2) + 1 + t0 + p];

    ull acc0[4], acc1[4];
    float cnt[4];
    #pragma unroll
    for (int p = 0; p < 4; ++p) { acc0[p] = 0ull; acc1[p] = 0ull; cnt[p] = 0.0f; }

    #pragma unroll
    for (int ky = 0; ky < 3; ++ky) {
        #pragma unroll
        for (int kx = 0; kx < 3; ++kx) {
            const int tap = ky * 3 + kx;
            const float* wsrow = sWs + tap * 4096 + o0;
            const float* vbase = sIn + ky * 64 * (TILE_W + 2) + t0 + kx;

            ull p0[4], p1[4];
            #pragma unroll
            for (int p = 0; p < 4; ++p) { p0[p] = 0ull; p1[p] = 0ull; }

            #pragma unroll 8
            for (int c = 0; c < 64; ++c) {
                float4 w4 = *reinterpret_cast<const float4*>(wsrow + c * 64);
                ull wA = pack2(w4.x, w4.y);
                ull wB = pack2(w4.z, w4.w);
                const float* vr = vbase + c * (TILE_W + 2);
                #pragma unroll
                for (int p = 0; p < 4; ++p) {
                    float v = vr[p];
                    ull vv = pack2(v, v);
                    p0[p] = fma2(wA, vv, p0[p]);
                    p1[p] = fma2(wB, vv, p1[p]);
                }
            }

            // gate the per-tap partial by mask equality, count matches
            const float* mrow = sM + ky * (TILE_W + 2) + t0 + kx;
            #pragma unroll
            for (int p = 0; p < 4; ++p) {
                float s = (mrow[p] == m0[p]) ? 1.0f : 0.0f;
                cnt[p] += s;
                ull ss = pack2(s, s);
                acc0[p] = fma2(p0[p], ss, acc0[p]);
                acc1[p] = fma2(p1[p], ss, acc1[p]);
            }
        }
    }

    // ---- epilogue: normalize, add bias, store ----
    float4 bs = *reinterpret_cast<const float4*>(bias + o0);
    float inv[4];
    #pragma unroll
    for (int p = 0; p < 4; ++p) inv[p] = 9.0f / cnt[p];  // cnt >= 1 always

    float vals[4][4];
    #pragma unroll
    for (int p = 0; p < 4; ++p) {
        float2 a0 = unpack2(acc0[p]);
        float2 a1 = unpack2(acc1[p]);
        vals[0][p] = a0.x * inv[p] + bs.x;
        vals[1][p] = a0.y * inv[p] + bs.y;
        vals[2][p] = a1.x * inv[p] + bs.z;
        vals[3][p] = a1.y * inv[p] + bs.w;
    }
    #pragma unroll
    for (int k = 0; k < 4; ++k) {
        int o = o0 + k;
        float* dst = out + ((b * OC + o) * HDIM + y) * WDIM + x0 + t0;
        *reinterpret_cast<float4*>(dst) =
            make_float4(vals[k][0], vals[k][1], vals[k][2], vals[k][3]);
    }

    // mask passthrough output (one o-group per pixel-group writes it)
    if (po == 0) {
        float* dst = out + OUT_MASK_OFF + (b * HDIM + y) * WDIM + x0 + t0;
        *reinterpret_cast<float4*>(dst) = make_float4(m0[0], m0[1], m0[2], m0[3]);
    }
}

extern "C" void kernel_launch(void* const* d_in, const int* in_sizes, int n_in,
                              void* d_out, int out_size) {
    const float* inp  = (const float*)d_in[0];
    const float* mask = (const float*)d_in[1];
    const float* conv = (const float*)d_in[2];
    const float* bias = (const float*)d_in[3];
    float* out = (float*)d_out;

    (void)in_sizes; (void)n_in; (void)out_size;

    cudaFuncSetAttribute(instconv_kernel,
                         cudaFuncAttributeMaxDynamicSharedMemorySize, SMEM_BYTES);

    wt_transpose<<<(WS_FLOATS + 255) / 256, 256>>>(conv);

    dim3 grid(WDIM / TILE_W, HDIM, BATCH);  // (2, 128, 8)
    instconv_kernel<<<grid, 256, SMEM_BYTES>>>(inp, mask, bias, out);
}

// round 2
// speedup vs baseline: 1.3509x; 1.3509x over previous
#include <cuda_runtime.h>

// InstanceConv on GB300 (sm_103a) — packed f32x2 FMA, fma-pipe-bound layout.
// out[b,o,y,x] = (9/cnt) * sum_{tap,c} s[tap]*W[o,c,tap]*inp[b,c,y+dy,x+dx] + bias[o]
// mask_out[b,0,y,x] = mask[b,y,x]
// B=8, C=64, OC=64, H=W=128, K=3, pad=1, stride=1.

#define BATCH 8
#define CH 64
#define OC 64
#define HDIM 128
#define WDIM 128
#define TILE_W 64
#define ROWS_PER_CTA 2
#define RS 68                     // padded smem row stride (16B aligned)

#define WS_FLOATS (9 * 64 * 64)            // 36864: [tap][c][o]
#define IN_FLOATS (4 * 64 * RS)            // 17408: [row][c][padded x]
#define MK_FLOATS (4 * RS)                 // 272:   [row][padded x]
#define SMEM_FLOATS (WS_FLOATS + IN_FLOATS + MK_FLOATS)
#define SMEM_BYTES (SMEM_FLOATS * 4)       // 218176 B

#define OUT_MASK_OFF (BATCH * OC * HDIM * WDIM)   // 8388608

typedef unsigned long long ull;

__device__ float g_wt[WS_FLOATS];

__device__ __forceinline__ ull pack2(float a, float b) {
    ull r;
    asm("mov.b64 %0, {%1, %2};" : "=l"(r) : "f"(a), "f"(b));
    return r;
}
__device__ __forceinline__ ull fma2(ull a, ull b, ull c) {
    ull d;
    asm("fma.rn.f32x2 %0, %1, %2, %3;" : "=l"(d) : "l"(a), "l"(b), "l"(c));
    return d;
}
__device__ __forceinline__ float2 unpack2(ull v) {
    float2 r;
    asm("mov.b64 {%0, %1}, %2;" : "=f"(r.x), "=f"(r.y) : "l"(v));
    return r;
}

// One-time weight transpose: conv[o][c][ky][kx] -> g_wt[tap][c][o].
__global__ void wt_transpose(const float* __restrict__ conv) {
    int i = blockIdx.x * 256 + threadIdx.x;
    if (i < WS_FLOATS) {
        int o   = i & 63;
        int c   = (i >> 6) & 63;
        int tap = i >> 12;
        g_wt[i] = conv[(o * 64 + c) * 9 + tap];
    }
}

__global__ __launch_bounds__(512, 1)
void instconv_kernel(const float* __restrict__ inp,
                     const float* __restrict__ mask,
                     const float* __restrict__ bias,
                     float* __restrict__ out) {
    extern __shared__ float sm[];
    float* sWs = sm;                          // [9][64][64]
    float* sIn = sm + WS_FLOATS;              // [4][64][RS]
    float* sM  = sm + WS_FLOATS + IN_FLOATS;  // [4][RS]

    const int tid = threadIdx.x;
    const int b  = blockIdx.z;
    const int y0 = blockIdx.y * ROWS_PER_CTA;
    const int x0 = blockIdx.x * TILE_W;

    // ---- stage weights (coalesced float4 copies) ----
    {
        const float4* gw4 = reinterpret_cast<const float4*>(g_wt);
        float4* sw4 = reinterpret_cast<float4*>(sWs);
        #pragma unroll 4
        for (int i = tid; i < WS_FLOATS / 4; i += 512) sw4[i] = gw4[i];
    }

    // ---- stage input window: 4 rows x 64 ch x RS padded pixels ----
    for (int i = tid; i < IN_FLOATS; i += 512) {
        int xx = i % RS;            // logical x = x0 + xx - 1
        int rc = i / RS;
        int c  = rc & 63;
        int r  = rc >> 6;           // 0..3 -> src row y0 + r - 1
        int ys = y0 + r - 1;
        int xs = x0 + xx - 1;
        float v = 0.0f;
        if ((unsigned)ys < (unsigned)HDIM && (unsigned)xs < (unsigned)WDIM)
            v = inp[((b * CH + c) * HDIM + ys) * WDIM + xs];
        sIn[i] = v;
    }

    // ---- stage mask window (fill -1 OOB -> never equals center, s=0) ----
    for (int i = tid; i < MK_FLOATS; i += 512) {
        int xx = i % RS;
        int r  = i / RS;
        int ys = y0 + r - 1;
        int xs = x0 + xx - 1;
        float v = -1.0f;
        if ((unsigned)ys < (unsigned)HDIM && (unsigned)xs < (unsigned)WDIM)
            v = mask[(b * HDIM + ys) * WDIM + xs];
        sM[i] = v;
    }
    __syncthreads();

    // thread tile: 4 output channels x 4 pixels, in output row r.
    const int r  = tid >> 8;          // 0 or 1
    const int t2 = tid & 255;
    const int po = t2 & 15;           // o-group
    const int pp = t2 >> 4;           // pixel-group
    const int o0 = po * 4;
    const int t0 = pp * 4;

    float m0[4];
    #pragma unroll
    for (int p = 0; p < 4; ++p) m0[p] = sM[(r + 1) * RS + 1 + t0 + p];

    ull acc[4][2];                    // [pixel][o-pair(0:o0..o0+1, 1:o0+2..o0+3)]
    float cnt[4];
    #pragma unroll
    for (int p = 0; p < 4; ++p) { acc[p][0] = 0ull; acc[p][1] = 0ull; cnt[p] = 0.0f; }

    #pragma unroll
    for (int ky = 0; ky < 3; ++ky) {
        const float* wbase = sWs + (ky * 3) * 4096 + o0;
        const float* vrow  = sIn + (r + ky) * 64 * RS + t0;

        // per-kx partial accumulators (gated after the c-loop)
        ull part[3][4][2];
        #pragma unroll
        for (int kx = 0; kx < 3; ++kx)
            #pragma unroll
            for (int p = 0; p < 4; ++p) { part[kx][p][0] = 0ull; part[kx][p][1] = 0ull; }

        #pragma unroll 2
        for (int c = 0; c < 64; ++c) {
            // 8 pixel values covering x = t0-1 .. t0+6 (only v0..v5 used)
            float4 va = *reinterpret_cast<const float4*>(vrow + c * RS);
            float4 vb = *reinterpret_cast<const float4*>(vrow + c * RS + 4);
            ull vd[6];
            vd[0] = pack2(va.x, va.x);
            vd[1] = pack2(va.y, va.y);
            vd[2] = pack2(va.z, va.z);
            vd[3] = pack2(va.w, va.w);
            vd[4] = pack2(vb.x, vb.x);
            vd[5] = pack2(vb.y, vb.y);

            #pragma unroll
            for (int kx = 0; kx < 3; ++kx) {
                float4 w4 = *reinterpret_cast<const float4*>(wbase + kx * 4096 + c * 64);
                ull wA = pack2(w4.x, w4.y);   // aligned pair from LDS.128 quad
                ull wB = pack2(w4.z, w4.w);
                #pragma unroll
                for (int p = 0; p < 4; ++p) {
                    part[kx][p][0] = fma2(wA, vd[p + kx], part[kx][p][0]);
                    part[kx][p][1] = fma2(wB, vd[p + kx], part[kx][p][1]);
                }
            }
        }

        // gate by mask equality, accumulate
        const float* mrow = sM + (r + ky) * RS + t0;
        #pragma unroll
        for (int kx = 0; kx < 3; ++kx) {
            #pragma unroll
            for (int p = 0; p < 4; ++p) {
                float s = (mrow[p + kx] == m0[p]) ? 1.0f : 0.0f;
                cnt[p] += s;
                ull ss = pack2(s, s);
                acc[p][0] = fma2(part[kx][p][0], ss, acc[p][0]);
                acc[p][1] = fma2(part[kx][p][1], ss, acc[p][1]);
            }
        }
    }

    // ---- epilogue: normalize, add bias, store ----
    const int y = y0 + r;
    float4 bs = *reinterpret_cast<const float4*>(bias + o0);
    float vals[4][4];
    #pragma unroll
    for (int p = 0; p < 4; ++p) {
        float inv = 9.0f / cnt[p];    // cnt >= 1 (center always matches)
        float2 a0 = unpack2(acc[p][0]);
        float2 a1 = unpack2(acc[p][1]);
        vals[0][p] = a0.x * inv + bs.x;
        vals[1][p] = a0.y * inv + bs.y;
        vals[2][p] = a1.x * inv + bs.z;
        vals[3][p] = a1.y * inv + bs.w;
    }
    #pragma unroll
    for (int k = 0; k < 4; ++k) {
        int o = o0 + k;
        float* dst = out + ((b * OC + o) * HDIM + y) * WDIM + x0 + t0;
        *reinterpret_cast<float4*>(dst) =
            make_float4(vals[k][0], vals[k][1], vals[k][2], vals[k][3]);
    }

    // mask passthrough output
    if (po == 0) {
        float* dst = out + OUT_MASK_OFF + (b * HDIM + y) * WDIM + x0 + t0;
        *reinterpret_cast<float4*>(dst) = make_float4(m0[0], m0[1], m0[2], m0[3]);
    }
}

extern "C" void kernel_launch(void* const* d_in, const int* in_sizes, int n_in,
                              void* d_out, int out_size) {
    const float* inp  = (const float*)d_in[0];
    const float* mask = (const float*)d_in[1];
    const float* conv = (const float*)d_in[2];
    const float* bias = (const float*)d_in[3];
    float* out = (float*)d_out;

    (void)in_sizes; (void)n_in; (void)out_size;

    cudaFuncSetAttribute(instconv_kernel,
                         cudaFuncAttributeMaxDynamicSharedMemorySize, SMEM_BYTES);

    wt_transpose<<<(WS_FLOATS + 255) / 256, 256>>>(conv);

    dim3 grid(WDIM / TILE_W, HDIM / ROWS_PER_CTA, BATCH);  // (2, 64, 8)
    instconv_kernel<<<grid, 512, SMEM_BYTES>>>(inp, mask, bias, out);
}

// round 5
// speedup vs baseline: 2.3566x; 1.7445x over previous
#include <cuda_runtime.h>
#include <cuda_bf16.h>
#include <cstdint>

// InstanceConv via warp-level mma.sync bf16-split GEMM (sm_103 base target —
// tcgen05 unavailable: harness compiles PTX at compute_103 without 'a').
// D[p,o] = sum_{tap,c} s_tap[p] * x[c, p+dx, y+dy] * W[o,c,tap]
// out = D * 9/cnt + bias;  mask_out = mask.
// B=8, C=64, OC=64, H=W=128, K=3, pad=1.

#define BATCH 8
#define CH 64
#define OCN 64
#define HDIM 128
#define WDIM 128
#define NTILES (BATCH * HDIM)       // 1024 row-tiles
#define GRID_MAIN 148
#define NTHREADS 256
#define OUT_MASK_OFF (BATCH * OCN * HDIM * WDIM)   // 8388608

// ---- smem layout (bytes) ----
// W tiles: [tap][plane][c:64] rows of 64 bf16, padded row stride 144B
#define WROW 144
#define WTILE (64 * WROW)            // 9216 per (tap,plane)
#define OFF_W 0
#define W_BYTES (18 * WTILE)         // 165888
// X planes: [xi:130] rows of 64 bf16 (c-contig), stride 144B
#define XROW 144
#define OFF_XH (OFF_W + W_BYTES)     // 165888
#define X_BYTES (130 * XROW)         // 18720
#define OFF_XL (OFF_XH + X_BYTES)    // 184608
#define XLO_DELTA (OFF_XL - OFF_XH)
#define OFF_M  (OFF_XL + X_BYTES)    // 203328: mask [3][132] f32
#define OFF_B  (OFF_M + 3 * 132 * 4) // 204912: bias [64] f32
#define SMEM_TOTAL (OFF_B + 256)     // 205168
// Dsm (epilogue, reuse X planes): [o:64][stride 132] f32 = 33792 <= 2*18720

__device__ uint32_t g_xthi[BATCH * HDIM * WDIM * 32];  // [b][y][x][c-pair] bf16 hi
__device__ uint32_t g_xtlo[BATCH * HDIM * WDIM * 32];  // lo plane
__device__ uint4 g_wimg[W_BYTES / 16];

__device__ __forceinline__ uint32_t smem_u32(const void* p) {
    uint32_t a;
    asm("{ .reg .u64 t; cvta.to.shared.u64 t, %1; cvt.u32.u64 %0, t; }" : "=r"(a) : "l"(p));
    return a;
}
__device__ __forceinline__ void ldsm_x4(uint32_t addr, uint32_t& r0, uint32_t& r1,
                                        uint32_t& r2, uint32_t& r3) {
    asm volatile("ldmatrix.sync.aligned.m8n8.x4.shared.b16 {%0,%1,%2,%3}, [%4];"
                 : "=r"(r0), "=r"(r1), "=r"(r2), "=r"(r3) : "r"(addr));
}
__device__ __forceinline__ void ldsm_x4t(uint32_t addr, uint32_t& r0, uint32_t& r1,
                                         uint32_t& r2, uint32_t& r3) {
    asm volatile("ldmatrix.sync.aligned.m8n8.x4.trans.shared.b16 {%0,%1,%2,%3}, [%4];"
                 : "=r"(r0), "=r"(r1), "=r"(r2), "=r"(r3) : "r"(addr));
}
__device__ __forceinline__ void mma_bf16(float* d, const uint32_t* a, uint32_t b0, uint32_t b1) {
    asm volatile("mma.sync.aligned.m16n8k16.row.col.f32.bf16.bf16.f32 "
                 "{%0,%1,%2,%3}, {%4,%5,%6,%7}, {%8,%9}, {%0,%1,%2,%3};"
                 : "+f"(d[0]), "+f"(d[1]), "+f"(d[2]), "+f"(d[3])
                 : "r"(a[0]), "r"(a[1]), "r"(a[2]), "r"(a[3]), "r"(b0), "r"(b1));
}

// ---------------- prep kernels ----------------
// Transpose input to [b][y][x][c] bf16 hi/lo planes (c contiguous per row).
__global__ void xprep(const float* __restrict__ inp) {
    __shared__ float tile[64][129];
    const int tid = threadIdx.x;
    const int b = blockIdx.x >> 7, y = blockIdx.x & 127;
    #pragma unroll
    for (int i = 0; i < 32; ++i) {
        int idx = i * 256 + tid;
        int c = idx >> 7, x = idx & 127;
        tile[c][x] = inp[((b * CH + c) * HDIM + y) * WDIM + x];
    }
    __syncthreads();
    #pragma unroll
    for (int i = 0; i < 16; ++i) {
        int idx = i * 256 + tid;
        int x = idx >> 5, cw = idx & 31;
        float v0 = tile[2 * cw][x], v1 = tile[2 * cw + 1][x];
        __nv_bfloat16 h0 = __float2bfloat16(v0);
        __nv_bfloat16 h1 = __float2bfloat16(v1);
        __nv_bfloat16 l0 = __float2bfloat16(v0 - __bfloat162float(h0));
        __nv_bfloat16 l1 = __float2bfloat16(v1 - __bfloat162float(h1));
        int base = (blockIdx.x * 128 + x) * 32 + cw;
        g_xthi[base] = (uint32_t)__bfloat16_as_ushort(h0) |
                       ((uint32_t)__bfloat16_as_ushort(h1) << 16);
        g_xtlo[base] = (uint32_t)__bfloat16_as_ushort(l0) |
                       ((uint32_t)__bfloat16_as_ushort(l1) << 16);
    }
}

// Weight split: conv[o][c][tap] -> [tap][plane][c][o] bf16, 144B row stride.
__global__ void wprep(const float* __restrict__ conv) {
    int i = blockIdx.x * 256 + threadIdx.x;
    if (i < 9 * 64 * 64) {
        int o = i & 63, c = (i >> 6) & 63, tap = i >> 12;
        float w = conv[(o * 64 + c) * 9 + tap];
        __nv_bfloat16 h = __float2bfloat16(w);
        __nv_bfloat16 l = __float2bfloat16(w - __bfloat162float(h));
        unsigned short* img = (unsigned short*)g_wimg;
        img[((tap * 2 + 0) * WTILE + c * WROW + o * 2) >> 1] = __bfloat16_as_ushort(h);
        img[((tap * 2 + 1) * WTILE + c * WROW + o * 2) >> 1] = __bfloat16_as_ushort(l);
    }
}

// ---------------- main persistent kernel ----------------
__global__ __launch_bounds__(NTHREADS, 1)
void instconv_mma(const float* __restrict__ mask,
                  const float* __restrict__ bias,
                  float* __restrict__ out) {
    extern __shared__ char smem[];
    const uint32_t sb = smem_u32(smem);
    const int tid = threadIdx.x;
    const int wid = tid >> 5;
    const int lane = tid & 31;
    const int g = lane >> 2;
    const int t2 = (lane & 3) * 2;
    const int p0 = wid * 16;

    // stage weights once (persist)
    {
        const uint4* src = g_wimg;
        uint4* dst = (uint4*)(smem + OFF_W);
        #pragma unroll 4
        for (int i = tid; i < W_BYTES / 16; i += NTHREADS) dst[i] = src[i];
    }
    if (tid < 64) ((float*)(smem + OFF_B))[tid] = bias[tid];

    float* sM = (float*)(smem + OFF_M);
    const float* sB = (const float*)(smem + OFF_B);
    uint32_t* sXH = (uint32_t*)(smem + OFF_XH);

    // per-lane ldmatrix base addresses
    const uint32_t aBase = sb + OFF_XH + (uint32_t)((p0 + (lane & 15)) * XROW + (lane >> 4) * 16);
    const uint32_t wBase = sb + OFF_W + (uint32_t)((lane & 15) * WROW + (lane >> 4) * 16);

    for (int t = blockIdx.x; t < NTILES; t += GRID_MAIN) {
        const int b = t >> 7;
        const int y = t & 127;

        // stage mask window [3][132], fill -1 (never equals center)
        for (int i = tid; i < 3 * 132; i += NTHREADS) {
            int r = i / 132, xi = i - r * 132;
            int ys = y + r - 1, xs = xi - 1;
            float v = -1.0f;
            if ((unsigned)ys < (unsigned)HDIM && (unsigned)xs < (unsigned)WDIM)
                v = mask[(b * HDIM + ys) * WDIM + xs];
            sM[i] = v;
        }

        float D[8][4];
        #pragma unroll
        for (int nb = 0; nb < 8; ++nb)
            #pragma unroll
            for (int j = 0; j < 4; ++j) D[nb][j] = 0.0f;

        for (int ky = 0; ky < 3; ++ky) {
            __syncthreads();   // mask ready (ky0) / X & Dsm free
            // stage X row (ky): [xi 0..129][c] hi and lo planes
            {
                const int ys = y + ky - 1;
                const bool yok = (unsigned)ys < (unsigned)HDIM;
                const uint32_t gbase = (uint32_t)(((b * HDIM + (yok ? ys : 0)) * WDIM) * 32);
                for (int i = tid; i < 130 * 32; i += NTHREADS) {
                    int xi = i >> 5, w = i & 31;
                    int xs = xi - 1;
                    uint32_t vh = 0, vl = 0;
                    if (yok && (unsigned)xs < (unsigned)WDIM) {
                        vh = g_xthi[gbase + xs * 32 + w];
                        vl = g_xtlo[gbase + xs * 32 + w];
                    }
                    sXH[(xi * XROW) / 4 + w] = vh;
                    sXH[(XLO_DELTA + xi * XROW) / 4 + w] = vl;
                }
            }
            __syncthreads();   // X ready

            const float m0A = sM[132 + p0 + g + 1];
            const float m0B = sM[132 + p0 + g + 9];

            #pragma unroll
            for (int kx = 0; kx < 3; ++kx) {
                const int tap = ky * 3 + kx;
                const uint32_t mA = (sM[ky * 132 + p0 + g + kx] == m0A) ? 0xFFFFFFFFu : 0u;
                const uint32_t mB = (sM[ky * 132 + p0 + g + 8 + kx] == m0B) ? 0xFFFFFFFFu : 0u;
                const uint32_t aT = aBase + (uint32_t)(kx * XROW);
                const uint32_t wT = wBase + (uint32_t)(tap * 2 * WTILE);

                #pragma unroll
                for (int k = 0; k < 4; ++k) {
                    uint32_t ah[4], al[4];
                    ldsm_x4(aT + 32 * k, ah[0], ah[1], ah[2], ah[3]);
                    ldsm_x4(aT + XLO_DELTA + 32 * k, al[0], al[1], al[2], al[3]);
                    ah[0] &= mA; ah[2] &= mA; ah[1] &= mB; ah[3] &= mB;
                    al[0] &= mA; al[2] &= mA; al[1] &= mB; al[3] &= mB;

                    const uint32_t wK = wT + (uint32_t)(k * 16 * WROW);
                    #pragma unroll
                    for (int nb2 = 0; nb2 < 4; ++nb2) {
                        uint32_t b0, b1, b2, b3;
                        ldsm_x4t(wK + nb2 * 32, b0, b1, b2, b3);
                        mma_bf16(D[nb2 * 2],     ah, b0, b1);
                        mma_bf16(D[nb2 * 2 + 1], ah, b2, b3);
                        mma_bf16(D[nb2 * 2],     al, b0, b1);
                        mma_bf16(D[nb2 * 2 + 1], al, b2, b3);
                    }
                    #pragma unroll
                    for (int nb2 = 0; nb2 < 4; ++nb2) {
                        uint32_t b0, b1, b2, b3;
                        ldsm_x4t(wK + WTILE + nb2 * 32, b0, b1, b2, b3);
                        mma_bf16(D[nb2 * 2],     ah, b0, b1);
                        mma_bf16(D[nb2 * 2 + 1], ah, b2, b3);
                    }
                }
            }
        }

        // ---- epilogue ----
        __syncthreads();   // all LDSM on X done -> safe to reuse as Dsm
        float* Dsm = (float*)(smem + OFF_XH);   // [64][132] f32
        {
            float cA = 0.0f, cB = 0.0f;
            const float m0A = sM[132 + p0 + g + 1];
            const float m0B = sM[132 + p0 + g + 9];
            #pragma unroll
            for (int ky2 = 0; ky2 < 3; ++ky2)
                #pragma unroll
                for (int kx2 = 0; kx2 < 3; ++kx2) {
                    cA += (sM[ky2 * 132 + p0 + g + kx2] == m0A) ? 1.0f : 0.0f;
                    cB += (sM[ky2 * 132 + p0 + g + 8 + kx2] == m0B) ? 1.0f : 0.0f;
                }
            const float invA = 9.0f / cA, invB = 9.0f / cB;  // cnt >= 1
            #pragma unroll
            for (int nb = 0; nb < 8; ++nb) {
                const int o0 = nb * 8 + t2;
                const float b0 = sB[o0], b1 = sB[o0 + 1];
                Dsm[o0 * 132 + p0 + g]           = D[nb][0] * invA + b0;
                Dsm[(o0 + 1) * 132 + p0 + g]     = D[nb][1] * invA + b1;
                Dsm[o0 * 132 + p0 + g + 8]       = D[nb][2] * invB + b0;
                Dsm[(o0 + 1) * 132 + p0 + g + 8] = D[nb][3] * invB + b1;
            }
        }
        __syncthreads();

        {   // coalesced output
            const int o = tid >> 2, q = tid & 3;
            const float4* src = (const float4*)(Dsm + o * 132 + q * 32);
            float4* dst = (float4*)(out + (((size_t)b * OCN + o) * HDIM + y) * WDIM + q * 32);
            #pragma unroll
            for (int j = 0; j < 8; ++j) dst[j] = src[j];
            if (tid < 128)
                out[OUT_MASK_OFF + (b * HDIM + y) * WDIM + tid] = sM[132 + tid + 1];
        }
        __syncthreads();   // protect sM / Dsm before next tile staging
    }
}

extern "C" void kernel_launch(void* const* d_in, const int* in_sizes, int n_in,
                              void* d_out, int out_size) {
    const float* inp  = (const float*)d_in[0];
    const float* mask = (const float*)d_in[1];
    const float* conv = (const float*)d_in[2];
    const float* bias = (const float*)d_in[3];
    float* out = (float*)d_out;
    (void)in_sizes; (void)n_in; (void)out_size;

    cudaFuncSetAttribute(instconv_mma,
                         cudaFuncAttributeMaxDynamicSharedMemorySize, SMEM_TOTAL);

    xprep<<<BATCH * HDIM, 256>>>(inp);
    wprep<<<(9 * 64 * 64 + 255) / 256, 256>>>(conv);
    instconv_mma<<<GRID_MAIN, NTHREADS, SMEM_TOTAL>>>(mask, bias, out);
}

// round 6
// speedup vs baseline: 2.5604x; 1.0865x over previous
#include <cuda_runtime.h>
#include <cuda_bf16.h>
#include <cstdint>

// InstanceConv via warp-level mma.sync bf16-split GEMM (compute_103-safe).
// Round 6: 2 output rows/CTA, 32 px per warp (2 A-fragment groups) to halve
// W-fragment LDSM bandwidth; W stored unpadded+swizzled; cp.async staging.
// B=8, C=64, OC=64, H=W=128, K=3, pad=1.

#define BATCH 8
#define CH 64
#define OCN 64
#define HDIM 128
#define WDIM 128
#define NTILES2 (BATCH * HDIM / 2)   // 512 two-row tiles
#define GRID_MAIN 148
#define NTHREADS 256
#define OUT_MASK_OFF (BATCH * OCN * HDIM * WDIM)   // 8388608

// ---- smem layout (bytes) ----
// W: [tap][plane] 64(c) x 64(o) bf16, 128B rows, XOR-swizzled chunks. 18*8192.
#define OFF_W 0
#define W_BYTES (18 * 8192)              // 147456
// X: 2 slots x 2 planes x [xi:130][c:64] bf16, 144B padded rows.
#define XROW 144
#define X_PLANE (130 * XROW)             // 18720
#define X_SLOT (2 * X_PLANE)             // 37440
#define OFF_X (OFF_W + W_BYTES)          // 147456
#define X_BYTES (2 * X_SLOT)             // 74880
#define OFF_M (OFF_X + X_BYTES)          // 222336: mask [4][132] f32
#define OFF_B (OFF_M + 4 * 132 * 4)      // 224448: bias [64] f32
#define SMEM_TOTAL (OFF_B + 256)         // 224704
// Epilogue Dsm reuses X: [2 rows][64 oc][132] f32 = 67584 <= 74880.
#define DSM_ROW 8448                     // floats per row slab (64*132)

__device__ uint32_t g_xthi[BATCH * HDIM * WDIM * 32];  // [b][y][x][c-pair] bf16 hi
__device__ uint32_t g_xtlo[BATCH * HDIM * WDIM * 32];  // lo plane
__device__ uint4 g_wimg[W_BYTES / 16];

__device__ __forceinline__ uint32_t smem_u32(const void* p) {
    uint32_t a;
    asm("{ .reg .u64 t; cvta.to.shared.u64 t, %1; cvt.u32.u64 %0, t; }" : "=r"(a) : "l"(p));
    return a;
}
__device__ __forceinline__ void ldsm_x4(uint32_t addr, uint32_t* r) {
    asm volatile("ldmatrix.sync.aligned.m8n8.x4.shared.b16 {%0,%1,%2,%3}, [%4];"
                 : "=r"(r[0]), "=r"(r[1]), "=r"(r[2]), "=r"(r[3]) : "r"(addr));
}
__device__ __forceinline__ void ldsm_x4t(uint32_t addr, uint32_t& r0, uint32_t& r1,
                                         uint32_t& r2, uint32_t& r3) {
    asm volatile("ldmatrix.sync.aligned.m8n8.x4.trans.shared.b16 {%0,%1,%2,%3}, [%4];"
                 : "=r"(r0), "=r"(r1), "=r"(r2), "=r"(r3) : "r"(addr));
}
__device__ __forceinline__ void mma_bf16(float* d, const uint32_t* a, uint32_t b0, uint32_t b1) {
    asm volatile("mma.sync.aligned.m16n8k16.row.col.f32.bf16.bf16.f32 "
                 "{%0,%1,%2,%3}, {%4,%5,%6,%7}, {%8,%9}, {%0,%1,%2,%3};"
                 : "+f"(d[0]), "+f"(d[1]), "+f"(d[2]), "+f"(d[3])
                 : "r"(a[0]), "r"(a[1]), "r"(a[2]), "r"(a[3]), "r"(b0), "r"(b1));
}
__device__ __forceinline__ void cpasync16(uint32_t d, const void* s, bool v) {
    asm volatile("cp.async.ca.shared.global [%0], [%1], 16, %2;"
                 :: "r"(d), "l"(s), "r"(v ? 16 : 0) : "memory");
}

// ---------------- prep kernels ----------------
// Transpose input to [b][y][x][c] bf16 hi/lo planes (c contiguous per row).
__global__ void xprep(const float* __restrict__ inp) {
    __shared__ float tile[64][129];
    const int tid = threadIdx.x;
    const int b = blockIdx.x >> 7, y = blockIdx.x & 127;
    #pragma unroll
    for (int i = 0; i < 32; ++i) {
        int idx = i * 256 + tid;
        int c = idx >> 7, x = idx & 127;
        tile[c][x] = inp[((b * CH + c) * HDIM + y) * WDIM + x];
    }
    __syncthreads();
    #pragma unroll
    for (int i = 0; i < 16; ++i) {
        int idx = i * 256 + tid;
        int x = idx >> 5, cw = idx & 31;
        float v0 = tile[2 * cw][x], v1 = tile[2 * cw + 1][x];
        __nv_bfloat16 h0 = __float2bfloat16(v0);
        __nv_bfloat16 h1 = __float2bfloat16(v1);
        __nv_bfloat16 l0 = __float2bfloat16(v0 - __bfloat162float(h0));
        __nv_bfloat16 l1 = __float2bfloat16(v1 - __bfloat162float(h1));
        int base = (blockIdx.x * 128 + x) * 32 + cw;
        g_xthi[base] = (uint32_t)__bfloat16_as_ushort(h0) |
                       ((uint32_t)__bfloat16_as_ushort(h1) << 16);
        g_xtlo[base] = (uint32_t)__bfloat16_as_ushort(l0) |
                       ((uint32_t)__bfloat16_as_ushort(l1) << 16);
    }
}

// Weight split -> swizzled [tap][plane][c:64 rows x 128B] tiles.
// byte = c*128 + (((o>>3) ^ (c&7)) << 4) + (o&7)*2
__global__ void wprep(const float* __restrict__ conv) {
    int i = blockIdx.x * 256 + threadIdx.x;
    if (i < 9 * 64 * 64) {
        int o = i & 63, c = (i >> 6) & 63, tap = i >> 12;
        float w = conv[(o * 64 + c) * 9 + tap];
        __nv_bfloat16 h = __float2bfloat16(w);
        __nv_bfloat16 l = __float2bfloat16(w - __bfloat162float(h));
        unsigned short* img = (unsigned short*)g_wimg;
        uint32_t byte = (uint32_t)(c * 128 + ((((o >> 3) ^ (c & 7))) << 4) + (o & 7) * 2);
        img[((tap * 2 + 0) * 8192 + byte) >> 1] = __bfloat16_as_ushort(h);
        img[((tap * 2 + 1) * 8192 + byte) >> 1] = __bfloat16_as_ushort(l);
    }
}

// Stage one input row (hi+lo planes) into an X slot via cp.async (zero-fill OOB).
__device__ __forceinline__ void stage_row(uint32_t sb, int tid, int b, int ys, int slot) {
    const bool yok = (unsigned)ys < (unsigned)HDIM;
    const int ysafe = yok ? ys : 0;
    const char* gH = (const char*)(g_xthi + ((size_t)(b * HDIM + ysafe) * WDIM) * 32);
    const char* gL = (const char*)(g_xtlo + ((size_t)(b * HDIM + ysafe) * WDIM) * 32);
    const uint32_t dst = sb + OFF_X + (uint32_t)slot * X_SLOT;
    for (int i = tid; i < 130 * 8; i += NTHREADS) {
        int xi = i >> 3, q = i & 7;
        int xs = xi - 1;
        bool v = yok && (unsigned)xs < (unsigned)WDIM;
        int off = (v ? xs : 0) * 128 + q * 16;
        cpasync16(dst + xi * XROW + q * 16, gH + off, v);
        cpasync16(dst + X_PLANE + xi * XROW + q * 16, gL + off, v);
    }
    asm volatile("cp.async.commit_group;" ::: "memory");
}

// ---------------- main persistent kernel ----------------
__global__ __launch_bounds__(NTHREADS, 1)
void instconv_mma(const float* __restrict__ mask,
                  const float* __restrict__ bias,
                  float* __restrict__ out) {
    extern __shared__ char smem[];
    const uint32_t sb = smem_u32(smem);
    const int tid = threadIdx.x;
    const int wid = tid >> 5;
    const int lane = tid & 31;
    const int g = lane >> 2;
    const int t2 = (lane & 3) * 2;
    const int rg = wid >> 2;        // output row within pair
    const int p0 = (wid & 3) * 32;  // pixel chunk: groups at p0, p0+16
    const int lane15 = lane & 15;
    const int laneHi = (lane >> 4) * 16;

    // stage weights once (persist)
    {
        const uint4* src = g_wimg;
        uint4* dst = (uint4*)(smem + OFF_W);
        #pragma unroll 4
        for (int i = tid; i < W_BYTES / 16; i += NTHREADS) dst[i] = src[i];
    }
    if (tid < 64) ((float*)(smem + OFF_B))[tid] = bias[tid];

    float* sM = (float*)(smem + OFF_M);
    const float* sB = (const float*)(smem + OFF_B);

    // W lane-constant addresses (swizzle col term is lane-constant)
    const uint32_t wLane = sb + OFF_W + (uint32_t)(lane15 * 128);
    uint32_t wcs[4];
    #pragma unroll
    for (int nb2 = 0; nb2 < 4; ++nb2)
        wcs[nb2] = (uint32_t)((((nb2 * 2 + (lane >> 4)) ^ (lane & 7))) << 4);

    for (int t = blockIdx.x; t < NTILES2; t += GRID_MAIN) {
        const int b = t >> 6;
        const int y0 = (t & 63) * 2;

        // stage mask window [4][132], fill -1
        for (int i = tid; i < 4 * 132; i += NTHREADS) {
            int r = i >> 7;  // /132 approx; do exact:
            r = i / 132;
            int xi = i - r * 132;
            int ys = y0 + r - 1, xs = xi - 1;
            float v = -1.0f;
            if ((unsigned)ys < (unsigned)HDIM && (unsigned)xs < (unsigned)WDIM)
                v = mask[(b * HDIM + ys) * WDIM + xs];
            sM[i] = v;
        }
        // prologue: rows 0,1 -> slots 0,1
        stage_row(sb, tid, b, y0 - 1, 0);
        stage_row(sb, tid, b, y0, 1);

        float D[8][2][4];
        #pragma unroll
        for (int nb = 0; nb < 8; ++nb)
            #pragma unroll
            for (int gr = 0; gr < 2; ++gr)
                #pragma unroll
                for (int j = 0; j < 4; ++j) D[nb][gr][j] = 0.0f;

        const float* mrowC = sM + (rg + 1) * 132 + 1;

        for (int ky = 0; ky < 3; ++ky) {
            asm volatile("cp.async.wait_group 0;" ::: "memory");
            __syncthreads();   // staged data + mask visible

            const float* mrowT = sM + (rg + ky) * 132;
            const uint32_t slotBase = sb + OFF_X + (uint32_t)(((ky + rg) & 1) * X_SLOT);
            const uint32_t aRow = slotBase + (uint32_t)((p0 + lane15) * XROW + laneHi);

            #pragma unroll 1
            for (int kx = 0; kx < 3; ++kx) {
                uint32_t mk[4];
                #pragma unroll
                for (int j = 0; j < 4; ++j) {
                    float c0 = mrowC[p0 + g + j * 8];
                    float mt = mrowT[p0 + g + j * 8 + kx];
                    mk[j] = (mt == c0) ? 0xFFFFFFFFu : 0u;
                }
                const uint32_t aA = aRow + (uint32_t)(kx * XROW);
                const uint32_t wTap = wLane + (uint32_t)((ky * 3 + kx) * 16384);

                #pragma unroll
                for (int k = 0; k < 4; ++k) {
                    uint32_t ahA[4], alA[4], ahB[4], alB[4];
                    ldsm_x4(aA + k * 32, ahA);
                    ldsm_x4(aA + X_PLANE + k * 32, alA);
                    ldsm_x4(aA + 16 * XROW + k * 32, ahB);
                    ldsm_x4(aA + X_PLANE + 16 * XROW + k * 32, alB);
                    ahA[0] &= mk[0]; ahA[2] &= mk[0]; ahA[1] &= mk[1]; ahA[3] &= mk[1];
                    alA[0] &= mk[0]; alA[2] &= mk[0]; alA[1] &= mk[1]; alA[3] &= mk[1];
                    ahB[0] &= mk[2]; ahB[2] &= mk[2]; ahB[1] &= mk[3]; ahB[3] &= mk[3];
                    alB[0] &= mk[2]; alB[2] &= mk[2]; alB[1] &= mk[3]; alB[3] &= mk[3];

                    const uint32_t wk = wTap + (uint32_t)(k * 2048);
                    #pragma unroll
                    for (int nb2 = 0; nb2 < 4; ++nb2) {       // W hi plane
                        uint32_t b0, b1, b2, b3;
                        ldsm_x4t(wk + wcs[nb2], b0, b1, b2, b3);
                        mma_bf16(D[2 * nb2][0],     ahA, b0, b1);
                        mma_bf16(D[2 * nb2 + 1][0], ahA, b2, b3);
                        mma_bf16(D[2 * nb2][1],     ahB, b0, b1);
                        mma_bf16(D[2 * nb2 + 1][1], ahB, b2, b3);
                        mma_bf16(D[2 * nb2][0],     alA, b0, b1);
                        mma_bf16(D[2 * nb2 + 1][0], alA, b2, b3);
                        mma_bf16(D[2 * nb2][1],     alB, b0, b1);
                        mma_bf16(D[2 * nb2 + 1][1], alB, b2, b3);
                    }
                    #pragma unroll
                    for (int nb2 = 0; nb2 < 4; ++nb2) {       // W lo plane (hi A only)
                        uint32_t b0, b1, b2, b3;
                        ldsm_x4t(wk + 8192 + wcs[nb2], b0, b1, b2, b3);
                        mma_bf16(D[2 * nb2][0],     ahA, b0, b1);
                        mma_bf16(D[2 * nb2 + 1][0], ahA, b2, b3);
                        mma_bf16(D[2 * nb2][1],     ahB, b0, b1);
                        mma_bf16(D[2 * nb2 + 1][1], ahB, b2, b3);
                    }
                }
            }
            __syncthreads();   // done reading slot (ky&1)
            if (ky < 2) stage_row(sb, tid, b, y0 + ky + 1, ky & 1);
        }

        // ---- epilogue ----
        float* Dsm = (float*)(smem + OFF_X);   // [2][64][132] f32
        {
            float inv[4];
            #pragma unroll
            for (int j = 0; j < 4; ++j) {
                const int p = p0 + g + j * 8;
                const float m0 = sM[(rg + 1) * 132 + p + 1];
                float cnt = 0.0f;
                #pragma unroll
                for (int ky2 = 0; ky2 < 3; ++ky2)
                    #pragma unroll
                    for (int kx2 = 0; kx2 < 3; ++kx2)
                        cnt += (sM[(rg + ky2) * 132 + p + kx2] == m0) ? 1.0f : 0.0f;
                inv[j] = 9.0f / cnt;   // cnt >= 1
            }
            float* Drow = Dsm + rg * DSM_ROW;
            #pragma unroll
            for (int nb = 0; nb < 8; ++nb) {
                const int o0 = nb * 8 + t2;
                const float b0v = sB[o0], b1v = sB[o0 + 1];
                const int pA = p0 + g;
                Drow[o0 * 132 + pA]            = D[nb][0][0] * inv[0] + b0v;
                Drow[(o0 + 1) * 132 + pA]      = D[nb][0][1] * inv[0] + b1v;
                Drow[o0 * 132 + pA + 8]        = D[nb][0][2] * inv[1] + b0v;
                Drow[(o0 + 1) * 132 + pA + 8]  = D[nb][0][3] * inv[1] + b1v;
                Drow[o0 * 132 + pA + 16]       = D[nb][1][0] * inv[2] + b0v;
                Drow[(o0 + 1) * 132 + pA + 16] = D[nb][1][1] * inv[2] + b1v;
                Drow[o0 * 132 + pA + 24]       = D[nb][1][2] * inv[3] + b0v;
                Drow[(o0 + 1) * 132 + pA + 24] = D[nb][1][3] * inv[3] + b1v;
            }
        }
        __syncthreads();

        {   // coalesced output: 2 rows x 64 oc x 128 px
            const int o = tid >> 2, q = tid & 3;
            #pragma unroll
            for (int r = 0; r < 2; ++r) {
                const float4* src = (const float4*)(Dsm + r * DSM_ROW + o * 132 + q * 32);
                float4* dst = (float4*)(out + (((size_t)b * OCN + o) * HDIM + y0 + r) * WDIM + q * 32);
                #pragma unroll
                for (int j = 0; j < 8; ++j) dst[j] = src[j];
            }
            const int r2 = tid >> 7, px = tid & 127;
            out[OUT_MASK_OFF + (b * HDIM + y0 + r2) * WDIM + px] = sM[(r2 + 1) * 132 + px + 1];
        }
        __syncthreads();   // protect sM / Dsm / X before next tile staging
    }
}

extern "C" void kernel_launch(void* const* d_in, const int* in_sizes, int n_in,
                              void* d_out, int out_size) {
    const float* inp  = (const float*)d_in[0];
    const float* mask = (const float*)d_in[1];
    const float* conv = (const float*)d_in[2];
    const float* bias = (const float*)d_in[3];
    float* out = (float*)d_out;
    (void)in_sizes; (void)n_in; (void)out_size;

    cudaFuncSetAttribute(instconv_mma,
                         cudaFuncAttributeMaxDynamicSharedMemorySize, SMEM_TOTAL);

    xprep<<<BATCH * HDIM, 256>>>(inp);
    wprep<<<(9 * 64 * 64 + 255) / 256, 256>>>(conv);
    instconv_mma<<<GRID_MAIN, NTHREADS, SMEM_TOTAL>>>(mask, bias, out);
}

// round 7
// speedup vs baseline: 3.5519x; 1.3872x over previous
#include <cuda_runtime.h>
#include <cuda_fp16.h>
#include <cstdint>

// InstanceConv via warp-level mma.sync f16 2-pass split GEMM (compute_103-safe).
// x = f16(hi) + f16(lo) (exact to ~22 bits), W = f16 (err ~2^-12).
// D[p,o] = sum_{tap,c} s_tap[p] * x[c,p+d] * W[o,c,tap];  out = D*9/cnt + bias.
// B=8, C=64, OC=64, H=W=128, K=3, pad=1.

#define BATCH 8
#define CH 64
#define OCN 64
#define HDIM 128
#define WDIM 128
#define NTILES2 (BATCH * HDIM / 2)   // 512 two-row tiles
#define GRID_MAIN 148
#define NTHREADS 256
#define OUT_MASK_OFF (BATCH * OCN * HDIM * WDIM)   // 8388608

// ---- smem layout (bytes) ----
// W: [tap] 64(c) x 64(o) f16, 128B rows, XOR-swizzled. 9*8192.
#define OFF_W 0
#define W_BYTES (9 * 8192)               // 73728
// X: 3 slots x 2 planes x [xi:130][c:64] f16, 144B padded rows.
#define XROW 144
#define X_PLANE (130 * XROW)             // 18720
#define X_SLOT (2 * X_PLANE)             // 37440
#define OFF_X (OFF_W + W_BYTES)          // 73728
#define X_BYTES (3 * X_SLOT)             // 112320
#define OFF_M (OFF_X + X_BYTES)          // 186048: mask [4][132] f32
#define OFF_B (OFF_M + 4 * 132 * 4)      // 188160: bias [64] f32
#define SMEM_TOTAL (OFF_B + 256)         // 188416
// Epilogue Dsm reuses X region: [2][64][132] f32 = 67584 <= 112320.
#define DSM_ROW 8448

__device__ uint32_t g_xthi[BATCH * HDIM * WDIM * 32];  // [b][y][x][c-pair] f16 hi
__device__ uint32_t g_xtlo[BATCH * HDIM * WDIM * 32];  // f16 lo plane
__device__ uint4 g_wimg[W_BYTES / 16];

__device__ __forceinline__ uint32_t smem_u32(const void* p) {
    uint32_t a;
    asm("{ .reg .u64 t; cvta.to.shared.u64 t, %1; cvt.u32.u64 %0, t; }" : "=r"(a) : "l"(p));
    return a;
}
__device__ __forceinline__ void ldsm_x4(uint32_t addr, uint32_t* r) {
    asm volatile("ldmatrix.sync.aligned.m8n8.x4.shared.b16 {%0,%1,%2,%3}, [%4];"
                 : "=r"(r[0]), "=r"(r[1]), "=r"(r[2]), "=r"(r[3]) : "r"(addr));
}
__device__ __forceinline__ void ldsm_x4t(uint32_t addr, uint32_t& r0, uint32_t& r1,
                                         uint32_t& r2, uint32_t& r3) {
    asm volatile("ldmatrix.sync.aligned.m8n8.x4.trans.shared.b16 {%0,%1,%2,%3}, [%4];"
                 : "=r"(r0), "=r"(r1), "=r"(r2), "=r"(r3) : "r"(addr));
}
__device__ __forceinline__ void mma_f16(float* d, const uint32_t* a, uint32_t b0, uint32_t b1) {
    asm volatile("mma.sync.aligned.m16n8k16.row.col.f32.f16.f16.f32 "
                 "{%0,%1,%2,%3}, {%4,%5,%6,%7}, {%8,%9}, {%0,%1,%2,%3};"
                 : "+f"(d[0]), "+f"(d[1]), "+f"(d[2]), "+f"(d[3])
                 : "r"(a[0]), "r"(a[1]), "r"(a[2]), "r"(a[3]), "r"(b0), "r"(b1));
}
__device__ __forceinline__ void cpasync16(uint32_t d, const void* s, bool v) {
    asm volatile("cp.async.ca.shared.global [%0], [%1], 16, %2;"
                 :: "r"(d), "l"(s), "r"(v ? 16 : 0) : "memory");
}

// ---------------- prep kernels ----------------
// Transpose input to [b][y][x][c] f16 hi/lo planes. Half-row tiles for occupancy.
__global__ void xprep(const float* __restrict__ inp) {
    __shared__ float tile[64][65];
    const int tid = threadIdx.x;
    const int blk = blockIdx.x;
    const int half = blk & 1, y = (blk >> 1) & 127, b = blk >> 8;
    const int x0 = half * 64;
    #pragma unroll
    for (int i = 0; i < 16; ++i) {
        int idx = i * 256 + tid;
        int c = idx >> 6, x = idx & 63;
        tile[c][x] = inp[((b * CH + c) * HDIM + y) * WDIM + x0 + x];
    }
    __syncthreads();
    #pragma unroll
    for (int i = 0; i < 8; ++i) {
        int idx = i * 256 + tid;
        int x = idx >> 5, cw = idx & 31;
        float v0 = tile[2 * cw][x], v1 = tile[2 * cw + 1][x];
        __half h0 = __float2half(v0);
        __half h1 = __float2half(v1);
        __half l0 = __float2half(v0 - __half2float(h0));
        __half l1 = __float2half(v1 - __half2float(h1));
        int base = (((b * HDIM + y) * WDIM) + x0 + x) * 32 + cw;
        g_xthi[base] = (uint32_t)__half_as_ushort(h0) |
                       ((uint32_t)__half_as_ushort(h1) << 16);
        g_xtlo[base] = (uint32_t)__half_as_ushort(l0) |
                       ((uint32_t)__half_as_ushort(l1) << 16);
    }
}

// Weight -> swizzled [tap][c:64 rows x 128B] f16 tiles.
// byte = c*128 + (((o>>3) ^ (c&7)) << 4) + (o&7)*2
__global__ void wprep(const float* __restrict__ conv) {
    int i = blockIdx.x * 256 + threadIdx.x;
    if (i < 9 * 64 * 64) {
        int o = i & 63, c = (i >> 6) & 63, tap = i >> 12;
        float w = conv[(o * 64 + c) * 9 + tap];
        __half h = __float2half(w);
        unsigned short* img = (unsigned short*)g_wimg;
        uint32_t byte = (uint32_t)(c * 128 + ((((o >> 3) ^ (c & 7))) << 4) + (o & 7) * 2);
        img[(tap * 8192 + byte) >> 1] = __half_as_ushort(h);
    }
}

// Stage one input row (hi+lo planes) into an X slot via cp.async (zero-fill OOB).
__device__ __forceinline__ void stage_row(uint32_t sb, int tid, int b, int ys, int slot) {
    const bool yok = (unsigned)ys < (unsigned)HDIM;
    const int ysafe = yok ? ys : 0;
    const char* gH = (const char*)(g_xthi + ((size_t)(b * HDIM + ysafe) * WDIM) * 32);
    const char* gL = (const char*)(g_xtlo + ((size_t)(b * HDIM + ysafe) * WDIM) * 32);
    const uint32_t dst = sb + OFF_X + (uint32_t)slot * X_SLOT;
    for (int i = tid; i < 130 * 8; i += NTHREADS) {
        int xi = i >> 3, q = i & 7;
        int xs = xi - 1;
        bool v = yok && (unsigned)xs < (unsigned)WDIM;
        int off = (v ? xs : 0) * 128 + q * 16;
        cpasync16(dst + xi * XROW + q * 16, gH + off, v);
        cpasync16(dst + X_PLANE + xi * XROW + q * 16, gL + off, v);
    }
    asm volatile("cp.async.commit_group;" ::: "memory");
}

// ---------------- main persistent kernel ----------------
__global__ __launch_bounds__(NTHREADS, 1)
void instconv_mma(const float* __restrict__ mask,
                  const float* __restrict__ bias,
                  float* __restrict__ out) {
    extern __shared__ char smem[];
    const uint32_t sb = smem_u32(smem);
    const int tid = threadIdx.x;
    const int wid = tid >> 5;
    const int lane = tid & 31;
    const int g = lane >> 2;
    const int t2 = (lane & 3) * 2;
    const int rg = wid >> 2;        // output row within pair
    const int p0 = (wid & 3) * 32;  // pixel chunk: A-groups at p0, p0+16
    const int lane15 = lane & 15;
    const int laneHi = (lane >> 4) * 16;

    // stage weights once (persist)
    {
        const uint4* src = g_wimg;
        uint4* dst = (uint4*)(smem + OFF_W);
        #pragma unroll 4
        for (int i = tid; i < W_BYTES / 16; i += NTHREADS) dst[i] = src[i];
    }
    if (tid < 64) ((float*)(smem + OFF_B))[tid] = bias[tid];

    float* sM = (float*)(smem + OFF_M);
    const float* sB = (const float*)(smem + OFF_B);

    // W lane-constant addresses (swizzle col term is lane-constant)
    const uint32_t wLane = sb + OFF_W + (uint32_t)(lane15 * 128);
    uint32_t wcs[4];
    #pragma unroll
    for (int nb2 = 0; nb2 < 4; ++nb2)
        wcs[nb2] = (uint32_t)((((nb2 * 2 + (lane >> 4)) ^ (lane & 7))) << 4);

    for (int t = blockIdx.x; t < NTILES2; t += GRID_MAIN) {
        const int b = t >> 6;
        const int y0 = (t & 63) * 2;

        // stage mask window [4][132], fill -1
        for (int i = tid; i < 4 * 132; i += NTHREADS) {
            int r = i / 132;
            int xi = i - r * 132;
            int ys = y0 + r - 1, xs = xi - 1;
            float v = -1.0f;
            if ((unsigned)ys < (unsigned)HDIM && (unsigned)xs < (unsigned)WDIM)
                v = mask[(b * HDIM + ys) * WDIM + xs];
            sM[i] = v;
        }
        // prologue: rows y0-1, y0, y0+1 -> slots 0,1,2
        stage_row(sb, tid, b, y0 - 1, 0);
        stage_row(sb, tid, b, y0, 1);
        stage_row(sb, tid, b, y0 + 1, 2);

        float D[8][2][4];
        #pragma unroll
        for (int nb = 0; nb < 8; ++nb)
            #pragma unroll
            for (int gr = 0; gr < 2; ++gr)
                #pragma unroll
                for (int j = 0; j < 4; ++j) D[nb][gr][j] = 0.0f;

        const float* mrowC = sM + (rg + 1) * 132 + 1;

        for (int ky = 0; ky < 3; ++ky) {
            // row for this ky step ready? (allow newest groups to stay pending)
            if (ky < 2) asm volatile("cp.async.wait_group 1;" ::: "memory");
            else        asm volatile("cp.async.wait_group 0;" ::: "memory");
            __syncthreads();   // staged data + mask visible

            const float* mrowT = sM + (rg + ky) * 132;
            const uint32_t slotBase = sb + OFF_X + (uint32_t)(((ky + rg) % 3) * X_SLOT);
            const uint32_t aRow = slotBase + (uint32_t)((p0 + lane15) * XROW + laneHi);

            #pragma unroll 1
            for (int kx = 0; kx < 3; ++kx) {
                uint32_t mk[4];
                #pragma unroll
                for (int j = 0; j < 4; ++j) {
                    float c0 = mrowC[p0 + g + j * 8];
                    float mt = mrowT[p0 + g + j * 8 + kx];
                    mk[j] = (mt == c0) ? 0xFFFFFFFFu : 0u;
                }
                const uint32_t aA = aRow + (uint32_t)(kx * XROW);
                const uint32_t wTap = wLane + (uint32_t)((ky * 3 + kx) * 8192);

                #pragma unroll
                for (int k = 0; k < 4; ++k) {
                    uint32_t ahA[4], alA[4], ahB[4], alB[4];
                    ldsm_x4(aA + k * 32, ahA);
                    ldsm_x4(aA + X_PLANE + k * 32, alA);
                    ldsm_x4(aA + 16 * XROW + k * 32, ahB);
                    ldsm_x4(aA + X_PLANE + 16 * XROW + k * 32, alB);
                    ahA[0] &= mk[0]; ahA[2] &= mk[0]; ahA[1] &= mk[1]; ahA[3] &= mk[1];
                    alA[0] &= mk[0]; alA[2] &= mk[0]; alA[1] &= mk[1]; alA[3] &= mk[1];
                    ahB[0] &= mk[2]; ahB[2] &= mk[2]; ahB[1] &= mk[3]; ahB[3] &= mk[3];
                    alB[0] &= mk[2]; alB[2] &= mk[2]; alB[1] &= mk[3]; alB[3] &= mk[3];

                    const uint32_t wk = wTap + (uint32_t)(k * 2048);
                    #pragma unroll
                    for (int nb2 = 0; nb2 < 4; ++nb2) {
                        uint32_t b0, b1, b2, b3;
                        ldsm_x4t(wk + wcs[nb2], b0, b1, b2, b3);
                        mma_f16(D[2 * nb2][0],     ahA, b0, b1);
                        mma_f16(D[2 * nb2 + 1][0], ahA, b2, b3);
                        mma_f16(D[2 * nb2][1],     ahB, b0, b1);
                        mma_f16(D[2 * nb2 + 1][1], ahB, b2, b3);
                        mma_f16(D[2 * nb2][0],     alA, b0, b1);
                        mma_f16(D[2 * nb2 + 1][0], alA, b2, b3);
                        mma_f16(D[2 * nb2][1],     alB, b0, b1);
                        mma_f16(D[2 * nb2 + 1][1], alB, b2, b3);
                    }
                }
            }
            __syncthreads();   // readers done with slot (ky%3)
            // stage row y0+2 (r=3) into slot 0 — hidden under ky=1 compute
            if (ky == 0) stage_row(sb, tid, b, y0 + 2, 0);
        }

        // ---- epilogue ----
        float* Dsm = (float*)(smem + OFF_X);   // [2][64][132] f32
        {
            float inv[4];
            #pragma unroll
            for (int j = 0; j < 4; ++j) {
                const int p = p0 + g + j * 8;
                const float m0 = sM[(rg + 1) * 132 + p + 1];
                float cnt = 0.0f;
                #pragma unroll
                for (int ky2 = 0; ky2 < 3; ++ky2)
                    #pragma unroll
                    for (int kx2 = 0; kx2 < 3; ++kx2)
                        cnt += (sM[(rg + ky2) * 132 + p + kx2] == m0) ? 1.0f : 0.0f;
                inv[j] = 9.0f / cnt;   // cnt >= 1
            }
            float* Drow = Dsm + rg * DSM_ROW;
            #pragma unroll
            for (int nb = 0; nb < 8; ++nb) {
                const int o0 = nb * 8 + t2;
                const float b0v = sB[o0], b1v = sB[o0 + 1];
                const int pA = p0 + g;
                Drow[o0 * 132 + pA]            = D[nb][0][0] * inv[0] + b0v;
                Drow[(o0 + 1) * 132 + pA]      = D[nb][0][1] * inv[0] + b1v;
                Drow[o0 * 132 + pA + 8]        = D[nb][0][2] * inv[1] + b0v;
                Drow[(o0 + 1) * 132 + pA + 8]  = D[nb][0][3] * inv[1] + b1v;
                Drow[o0 * 132 + pA + 16]       = D[nb][1][0] * inv[2] + b0v;
                Drow[(o0 + 1) * 132 + pA + 16] = D[nb][1][1] * inv[2] + b1v;
                Drow[o0 * 132 + pA + 24]       = D[nb][1][2] * inv[3] + b0v;
                Drow[(o0 + 1) * 132 + pA + 24] = D[nb][1][3] * inv[3] + b1v;
            }
        }
        __syncthreads();

        {   // coalesced output: 2 rows x 64 oc x 128 px + mask rows
            const int o = tid >> 2, q = tid & 3;
            #pragma unroll
            for (int r = 0; r < 2; ++r) {
                const float4* src = (const float4*)(Dsm + r * DSM_ROW + o * 132 + q * 32);
                float4* dst = (float4*)(out + (((size_t)b * OCN + o) * HDIM + y0 + r) * WDIM + q * 32);
                #pragma unroll
                for (int j = 0; j < 8; ++j) dst[j] = src[j];
            }
            const int r2 = tid >> 7, px = tid & 127;
            out[OUT_MASK_OFF + (b * HDIM + y0 + r2) * WDIM + px] = sM[(r2 + 1) * 132 + px + 1];
        }
        __syncthreads();   // protect sM / Dsm / X before next tile staging
    }
}

extern "C" void kernel_launch(void* const* d_in, const int* in_sizes, int n_in,
                              void* d_out, int out_size) {
    const float* inp  = (const float*)d_in[0];
    const float* mask = (const float*)d_in[1];
    const float* conv = (const float*)d_in[2];
    const float* bias = (const float*)d_in[3];
    float* out = (float*)d_out;
    (void)in_sizes; (void)n_in; (void)out_size;

    cudaFuncSetAttribute(instconv_mma,
                         cudaFuncAttributeMaxDynamicSharedMemorySize, SMEM_TOTAL);

    xprep<<<BATCH * HDIM * 2, 256>>>(inp);
    wprep<<<(9 * 64 * 64 + 255) / 256, 256>>>(conv);
    instconv_mma<<<GRID_MAIN, NTHREADS, SMEM_TOTAL>>>(mask, bias, out);
}

// round 8
// speedup vs baseline: 5.9148x; 1.6653x over previous
#include <cuda_runtime.h>
#include <cuda_fp16.h>
#include <cstdint>

// InstanceConv via warp-level mma.sync f16 single-pass GEMM (compute_103-safe).
// x = f16, W = f16, fp32 accum. rel_err ~3e-4 (< 1e-3 threshold).
// D[p,o] = sum_{tap,c} s_tap[p] * x[c,p+d] * W[o,c,tap];  out = D*9/cnt + bias.
// B=8, C=64, OC=64, H=W=128, K=3, pad=1.

#define BATCH 8
#define CH 64
#define OCN 64
#define HDIM 128
#define WDIM 128
#define NTILES 1024                  // 2-row x 64-px tiles
#define GRID_MAIN 304                // 2 CTAs/SM x 152 SMs (GB300)
#define NTHREADS 256
#define OUT_MASK_OFF (BATCH * OCN * HDIM * WDIM)   // 8388608

// ---- smem layout (bytes) ----
#define OFF_W 0
#define W_BYTES (9 * 8192)               // 73728: [tap] 64(c)x64(o) f16, swizzled
#define XROW 144
#define X_PLANE (66 * XROW)              // 9504: one row slot [xi:66][c:64] f16
#define OFF_X (OFF_W + W_BYTES)          // 73728; 3 slots = 28512
#define X_REGION 34816                   // max(3*X_PLANE, Dsm 2*64*68*4)
#define OFF_M (OFF_X + X_REGION)         // 108544: mask [4][68] f32
#define OFF_B (OFF_M + 4 * 68 * 4)       // 109632: bias [64] f32
#define SMEM_TOTAL (OFF_B + 256)         // 109888  (x2 CTAs = 219776 <= 227KB)
#define DSM_ROW (64 * 68)                // floats per output-row slab

__device__ uint32_t g_xt[BATCH * HDIM * WDIM * 32];  // [b][y][x][c-pair] f16x2
__device__ uint4 g_wimg[W_BYTES / 16];

__device__ __forceinline__ uint32_t smem_u32(const void* p) {
    uint32_t a;
    asm("{ .reg .u64 t; cvta.to.shared.u64 t, %1; cvt.u32.u64 %0, t; }" : "=r"(a) : "l"(p));
    return a;
}
__device__ __forceinline__ void ldsm_x4(uint32_t addr, uint32_t* r) {
    asm volatile("ldmatrix.sync.aligned.m8n8.x4.shared.b16 {%0,%1,%2,%3}, [%4];"
                 : "=r"(r[0]), "=r"(r[1]), "=r"(r[2]), "=r"(r[3]) : "r"(addr));
}
__device__ __forceinline__ void ldsm_x4t(uint32_t addr, uint32_t& r0, uint32_t& r1,
                                         uint32_t& r2, uint32_t& r3) {
    asm volatile("ldmatrix.sync.aligned.m8n8.x4.trans.shared.b16 {%0,%1,%2,%3}, [%4];"
                 : "=r"(r0), "=r"(r1), "=r"(r2), "=r"(r3) : "r"(addr));
}
__device__ __forceinline__ void mma_f16(float* d, const uint32_t* a, uint32_t b0, uint32_t b1) {
    asm volatile("mma.sync.aligned.m16n8k16.row.col.f32.f16.f16.f32 "
                 "{%0,%1,%2,%3}, {%4,%5,%6,%7}, {%8,%9}, {%0,%1,%2,%3};"
                 : "+f"(d[0]), "+f"(d[1]), "+f"(d[2]), "+f"(d[3])
                 : "r"(a[0]), "r"(a[1]), "r"(a[2]), "r"(a[3]), "r"(b0), "r"(b1));
}
__device__ __forceinline__ void cpasync16(uint32_t d, const void* s, bool v) {
    asm volatile("cp.async.ca.shared.global [%0], [%1], 16, %2;"
                 :: "r"(d), "l"(s), "r"(v ? 16 : 0) : "memory");
}

// ---------------- combined prep kernel ----------------
// blocks [0, 2048): transpose input half-rows -> [b][y][x][c] f16 pairs.
// blocks [2048, 2192): weight split -> swizzled [tap][c:64 x 128B] f16 tiles.
__global__ void prep(const float* __restrict__ inp, const float* __restrict__ conv) {
    const int tid = threadIdx.x;
    if (blockIdx.x >= 2048) {
        int i = (blockIdx.x - 2048) * 256 + tid;
        if (i < 9 * 64 * 64) {
            int o = i & 63, c = (i >> 6) & 63, tap = i >> 12;
            __half h = __float2half(conv[(o * 64 + c) * 9 + tap]);
            unsigned short* img = (unsigned short*)g_wimg;
            uint32_t byte = (uint32_t)(c * 128 + ((((o >> 3) ^ (c & 7))) << 4) + (o & 7) * 2);
            img[(tap * 8192 + byte) >> 1] = __half_as_ushort(h);
        }
        return;
    }
    __shared__ float tile[64][65];
    const int blk = blockIdx.x;
    const int half = blk & 1, y = (blk >> 1) & 127, b = blk >> 8;
    const int x0 = half * 64;
    #pragma unroll
    for (int i = 0; i < 16; ++i) {
        int idx = i * 256 + tid;
        int c = idx >> 6, x = idx & 63;
        tile[c][x] = inp[((b * CH + c) * HDIM + y) * WDIM + x0 + x];
    }
    __syncthreads();
    #pragma unroll
    for (int i = 0; i < 8; ++i) {
        int idx = i * 256 + tid;
        int x = idx >> 5, cw = idx & 31;
        __half h0 = __float2half(tile[2 * cw][x]);
        __half h1 = __float2half(tile[2 * cw + 1][x]);
        g_xt[(((b * HDIM + y) * WDIM) + x0 + x) * 32 + cw] =
            (uint32_t)__half_as_ushort(h0) | ((uint32_t)__half_as_ushort(h1) << 16);
    }
}

// Stage one input row window (66 px from x0-1) into an X slot via cp.async.
__device__ __forceinline__ void stage_row(uint32_t sb, int tid, int b, int ys, int x0, int slot) {
    const bool yok = (unsigned)ys < (unsigned)HDIM;
    const int ysafe = yok ? ys : 0;
    const char* gX = (const char*)(g_xt + ((size_t)(b * HDIM + ysafe) * WDIM) * 32);
    const uint32_t dst = sb + OFF_X + (uint32_t)slot * X_PLANE;
    for (int i = tid; i < 66 * 8; i += NTHREADS) {
        int xi = i >> 3, q = i & 7;
        int xs = x0 + xi - 1;
        bool v = yok && (unsigned)xs < (unsigned)WDIM;
        cpasync16(dst + xi * XROW + q * 16, gX + (v ? xs : 0) * 128 + q * 16, v);
    }
    asm volatile("cp.async.commit_group;" ::: "memory");
}

// ---------------- main persistent kernel ----------------
__global__ __launch_bounds__(NTHREADS, 2)
void instconv_mma(const float* __restrict__ mask,
                  const float* __restrict__ bias,
                  float* __restrict__ out) {
    extern __shared__ char smem[];
    const uint32_t sb = smem_u32(smem);
    const int tid = threadIdx.x;
    const int wid = tid >> 5;
    const int lane = tid & 31;
    const int g = lane >> 2;
    const int t2 = (lane & 3) * 2;
    const int rg = wid >> 2;        // output row within pair (0/1)
    const int p0 = (wid & 3) * 16;  // 16-px group within the 64-px tile
    const int lane15 = lane & 15;
    const int laneHi = (lane >> 4) * 16;

    // stage weights once (persist)
    {
        const uint4* src = g_wimg;
        uint4* dst = (uint4*)(smem + OFF_W);
        #pragma unroll 4
        for (int i = tid; i < W_BYTES / 16; i += NTHREADS) dst[i] = src[i];
    }
    if (tid < 64) ((float*)(smem + OFF_B))[tid] = bias[tid];

    float* sM = (float*)(smem + OFF_M);
    const float* sB = (const float*)(smem + OFF_B);

    // W lane-constant swizzled addresses
    const uint32_t wLane = sb + OFF_W + (uint32_t)(lane15 * 128);
    uint32_t wcs[4];
    #pragma unroll
    for (int nb2 = 0; nb2 < 4; ++nb2)
        wcs[nb2] = (uint32_t)((((nb2 * 2 + (lane >> 4)) ^ (lane & 7))) << 4);

    for (int t = blockIdx.x; t < NTILES; t += GRID_MAIN) {
        const int b = t >> 7;
        const int rem = t & 127;
        const int y0 = (rem >> 1) * 2;
        const int x0 = (rem & 1) * 64;

        // stage mask window [4][68], fill -1
        for (int i = tid; i < 4 * 68; i += NTHREADS) {
            int r = i >> 6;  // approx; exact below
            r = i / 68;
            int xi = i - r * 68;
            int ys = y0 + r - 1, xs = x0 + xi - 1;
            float v = -1.0f;
            if ((unsigned)ys < (unsigned)HDIM && (unsigned)xs < (unsigned)WDIM && xi < 66)
                v = mask[(b * HDIM + ys) * WDIM + xs];
            sM[i] = v;
        }
        // prologue: rows y0-1, y0, y0+1 -> slots 0,1,2
        stage_row(sb, tid, b, y0 - 1, x0, 0);
        stage_row(sb, tid, b, y0, x0, 1);
        stage_row(sb, tid, b, y0 + 1, x0, 2);

        float D[8][4];
        #pragma unroll
        for (int nb = 0; nb < 8; ++nb)
            #pragma unroll
            for (int j = 0; j < 4; ++j) D[nb][j] = 0.0f;

        const float* mrowC = sM + (rg + 1) * 68 + 1;

        for (int ky = 0; ky < 3; ++ky) {
            if (ky < 2) asm volatile("cp.async.wait_group 1;" ::: "memory");
            else        asm volatile("cp.async.wait_group 0;" ::: "memory");
            __syncthreads();   // staged data + mask visible

            const float* mrowT = sM + (rg + ky) * 68;
            const uint32_t slotBase = sb + OFF_X + (uint32_t)(((ky + rg) % 3) * X_PLANE);
            const uint32_t aRow = slotBase + (uint32_t)((p0 + lane15) * XROW + laneHi);

            #pragma unroll 1
            for (int kx = 0; kx < 3; ++kx) {
                uint32_t mk0, mk1;
                {
                    float c0 = mrowC[p0 + g];
                    float c1 = mrowC[p0 + g + 8];
                    mk0 = (mrowT[p0 + g + kx] == c0) ? 0xFFFFFFFFu : 0u;
                    mk1 = (mrowT[p0 + g + 8 + kx] == c1) ? 0xFFFFFFFFu : 0u;
                }
                const uint32_t aA = aRow + (uint32_t)(kx * XROW);
                const uint32_t wTap = wLane + (uint32_t)((ky * 3 + kx) * 8192);

                #pragma unroll
                for (int k = 0; k < 4; ++k) {
                    uint32_t ah[4];
                    ldsm_x4(aA + k * 32, ah);
                    ah[0] &= mk0; ah[2] &= mk0; ah[1] &= mk1; ah[3] &= mk1;

                    const uint32_t wk = wTap + (uint32_t)(k * 2048);
                    #pragma unroll
                    for (int nb2 = 0; nb2 < 4; ++nb2) {
                        uint32_t b0, b1, b2, b3;
                        ldsm_x4t(wk + wcs[nb2], b0, b1, b2, b3);
                        mma_f16(D[2 * nb2],     ah, b0, b1);
                        mma_f16(D[2 * nb2 + 1], ah, b2, b3);
                    }
                }
            }
            __syncthreads();   // readers done with slot (ky+rg-1 set)
            if (ky == 0) stage_row(sb, tid, b, y0 + 2, x0, 0);
        }

        // ---- epilogue ----
        float* Dsm = (float*)(smem + OFF_X);   // [2][64][68] f32
        {
            float inv0, inv1;
            {
                const int pA = p0 + g, pB = p0 + g + 8;
                const float m0 = sM[(rg + 1) * 68 + pA + 1];
                const float m1 = sM[(rg + 1) * 68 + pB + 1];
                float c0 = 0.0f, c1 = 0.0f;
                #pragma unroll
                for (int ky2 = 0; ky2 < 3; ++ky2)
                    #pragma unroll
                    for (int kx2 = 0; kx2 < 3; ++kx2) {
                        c0 += (sM[(rg + ky2) * 68 + pA + kx2] == m0) ? 1.0f : 0.0f;
                        c1 += (sM[(rg + ky2) * 68 + pB + kx2] == m1) ? 1.0f : 0.0f;
                    }
                inv0 = 9.0f / c0; inv1 = 9.0f / c1;   // cnt >= 1
            }
            float* Drow = Dsm + rg * DSM_ROW;
            #pragma unroll
            for (int nb = 0; nb < 8; ++nb) {
                const int o0 = nb * 8 + t2;
                const float b0v = sB[o0], b1v = sB[o0 + 1];
                const int pA = p0 + g;
                Drow[o0 * 68 + pA]           = D[nb][0] * inv0 + b0v;
                Drow[(o0 + 1) * 68 + pA]     = D[nb][1] * inv0 + b1v;
                Drow[o0 * 68 + pA + 8]       = D[nb][2] * inv1 + b0v;
                Drow[(o0 + 1) * 68 + pA + 8] = D[nb][3] * inv1 + b1v;
            }
        }
        __syncthreads();

        {   // coalesced output: 2 rows x 64 oc x 64 px + mask rows
            const int o = tid >> 2, q = tid & 3;
            #pragma unroll
            for (int r = 0; r < 2; ++r) {
                const float4* src = (const float4*)(Dsm + r * DSM_ROW + o * 68 + q * 16);
                float4* dst = (float4*)(out + (((size_t)b * OCN + o) * HDIM + y0 + r) * WDIM + x0 + q * 16);
                #pragma unroll
                for (int j = 0; j < 4; ++j) dst[j] = src[j];
            }
            if (tid < 128) {
                const int r2 = tid >> 6, px = tid & 63;
                out[OUT_MASK_OFF + (b * HDIM + y0 + r2) * WDIM + x0 + px] =
                    sM[(r2 + 1) * 68 + px + 1];
            }
        }
        __syncthreads();   // protect sM / Dsm / X before next tile staging
    }
}

extern "C" void kernel_launch(void* const* d_in, const int* in_sizes, int n_in,
                              void* d_out, int out_size) {
    const float* inp  = (const float*)d_in[0];
    const float* mask = (const float*)d_in[1];
    const float* conv = (const float*)d_in[2];
    const float* bias = (const float*)d_in[3];
    float* out = (float*)d_out;
    (void)in_sizes; (void)n_in; (void)out_size;

    cudaFuncSetAttribute(instconv_mma,
                         cudaFuncAttributeMaxDynamicSharedMemorySize, SMEM_TOTAL);

    prep<<<2048 + 144, 256>>>(inp, conv);
    instconv_mma<<<GRID_MAIN, NTHREADS, SMEM_TOTAL>>>(mask, bias, out);
}